// round 1
// baseline (speedup 1.0000x reference)
#include <cuda_runtime.h>

// Problem constants
#define B_   8
#define C_   128
#define N_   4096      // 64*64
#define M_   1024      // 32*32 pooled
#define DQK  16        // C/8
#define DV   64        // C/2

// Scratch (device globals: allocation-free contract)
static __device__ float g_theta[B_ * N_ * DQK];   // [b][n][16]
static __device__ float g_phiT [B_ * DQK * M_];   // [b][j][m]  (channel-major)
static __device__ float g_gv   [B_ * M_ * DV];    // [b][m][64]
static __device__ float g_ov   [B_ * DV * N_];    // [b][c][n]

// ---------------------------------------------------------------------------
// Fast exp on the FMA pipe (avoids MUFU bottleneck: 33.5M exps).
// exp(v) = 2^t, t = v*log2(e); split t = n + g, |g|<=0.5 via magic-number
// round-to-nearest; 2^g by degree-5 Taylor of exp(g ln2); splice 2^n into
// the exponent bits. Rel err ~3e-6.
// ---------------------------------------------------------------------------
__device__ __forceinline__ float fast_exp(float v) {
    float t = fmaxf(v * 1.4426950408889634f, -126.0f);
    float r = t + 12582912.0f;                 // 1.5*2^23: RN -> integer in mantissa
    int   n = (__float_as_int(r) & 0x7FFFFF) - 0x400000;
    float g = t - (r - 12582912.0f);           // in [-0.5, 0.5]
    float u = g * 0.6931471805599453f;
    float p = 1.0f + u * (1.0f + u * (0.5f + u * (0.16666667f +
                      u * (0.041666667f + u * 0.0083333333f))));
    return __int_as_float(__float_as_int(p) + (n << 23));
}

// ---------------------------------------------------------------------------
// Kernel 1: theta[b][n][0..15] = W_theta @ x[:, n]
// grid (16, 8), 256 threads, thread-per-pixel
// ---------------------------------------------------------------------------
__global__ void k_theta(const float* __restrict__ x, const float* __restrict__ Wth) {
    __shared__ float Wt[128][16];              // transposed [c][o]
    int tid = threadIdx.x, b = blockIdx.y;
#pragma unroll
    for (int t = 0; t < 8; t++) {
        int e = t * 256 + tid;                 // e = o*128 + c
        Wt[e & 127][e >> 7] = Wth[e];
    }
    __syncthreads();
    int n = blockIdx.x * 256 + tid;
    const float* xp = x + ((size_t)b * C_) * N_ + n;
    float acc[16];
#pragma unroll
    for (int i = 0; i < 16; i++) acc[i] = 0.f;
#pragma unroll 4
    for (int c = 0; c < 128; c++) {
        float xv = xp[(size_t)c * N_];
#pragma unroll
        for (int u = 0; u < 4; u++) {
            float4 w = *(const float4*)&Wt[c][u * 4];
            acc[u*4+0] = fmaf(xv, w.x, acc[u*4+0]);
            acc[u*4+1] = fmaf(xv, w.y, acc[u*4+1]);
            acc[u*4+2] = fmaf(xv, w.z, acc[u*4+2]);
            acc[u*4+3] = fmaf(xv, w.w, acc[u*4+3]);
        }
    }
    float* dst = &g_theta[((size_t)b * N_ + n) * DQK];
#pragma unroll
    for (int u = 0; u < 4; u++)
        ((float4*)dst)[u] = make_float4(acc[u*4], acc[u*4+1], acc[u*4+2], acc[u*4+3]);
}

// ---------------------------------------------------------------------------
// Kernel 2: phi (pooled, channel-major) and g (pooled, key-major).
// 4 threads per pooled cell (one per 2x2 pixel), shuffle-max over the 4 lanes.
// grid (16, 8), 256 threads -> 64 cells/block.
// ---------------------------------------------------------------------------
__global__ void k_phig(const float* __restrict__ x,
                       const float* __restrict__ Wph,
                       const float* __restrict__ Wg) {
    __shared__ float Wpt[128][16];             // [c][o]
    __shared__ float Wgt[128][64];             // [c][o]
    int tid = threadIdx.x, b = blockIdx.y;
#pragma unroll
    for (int t = 0; t < 8; t++) {
        int e = t * 256 + tid;
        Wpt[e & 127][e >> 7] = Wph[e];
    }
#pragma unroll
    for (int t = 0; t < 32; t++) {
        int e = t * 256 + tid;                 // e = o*128 + c, o<64
        Wgt[e & 127][e >> 7] = Wg[e];
    }
    __syncthreads();

    int cell = blockIdx.x * 64 + (tid >> 2);
    int p    = tid & 3;
    int ph = cell >> 5, pw = cell & 31;
    int h = ph * 2 + (p >> 1), w = pw * 2 + (p & 1);
    int n = h * 64 + w;
    const float* xp = x + ((size_t)b * C_) * N_ + n;

    float ap[16], ag[64];
#pragma unroll
    for (int i = 0; i < 16; i++) ap[i] = 0.f;
#pragma unroll
    for (int i = 0; i < 64; i++) ag[i] = 0.f;

#pragma unroll 1
    for (int c = 0; c < 128; c++) {
        float xv = xp[(size_t)c * N_];
#pragma unroll
        for (int u = 0; u < 4; u++) {
            float4 wv = *(const float4*)&Wpt[c][u * 4];
            ap[u*4+0] = fmaf(xv, wv.x, ap[u*4+0]);
            ap[u*4+1] = fmaf(xv, wv.y, ap[u*4+1]);
            ap[u*4+2] = fmaf(xv, wv.z, ap[u*4+2]);
            ap[u*4+3] = fmaf(xv, wv.w, ap[u*4+3]);
        }
#pragma unroll
        for (int u = 0; u < 16; u++) {
            float4 wv = *(const float4*)&Wgt[c][u * 4];
            ag[u*4+0] = fmaf(xv, wv.x, ag[u*4+0]);
            ag[u*4+1] = fmaf(xv, wv.y, ag[u*4+1]);
            ag[u*4+2] = fmaf(xv, wv.z, ag[u*4+2]);
            ag[u*4+3] = fmaf(xv, wv.w, ag[u*4+3]);
        }
    }
    // 2x2 max across the 4 lanes of this cell
#pragma unroll
    for (int i = 0; i < 16; i++) {
        ap[i] = fmaxf(ap[i], __shfl_xor_sync(0xffffffffu, ap[i], 1));
        ap[i] = fmaxf(ap[i], __shfl_xor_sync(0xffffffffu, ap[i], 2));
    }
#pragma unroll
    for (int i = 0; i < 64; i++) {
        ag[i] = fmaxf(ag[i], __shfl_xor_sync(0xffffffffu, ag[i], 1));
        ag[i] = fmaxf(ag[i], __shfl_xor_sync(0xffffffffu, ag[i], 2));
    }
    if (p == 0) {
#pragma unroll
        for (int o = 0; o < 16; o++)
            g_phiT[((size_t)b * DQK + o) * M_ + cell] = ap[o];
        float* gd = &g_gv[((size_t)b * M_ + cell) * DV];
#pragma unroll
        for (int u = 0; u < 16; u++)
            ((float4*)gd)[u] = make_float4(ag[u*4], ag[u*4+1], ag[u*4+2], ag[u*4+3]);
    }
}

// ---------------------------------------------------------------------------
// Kernel 3: fused attention, two-pass softmax, unnormalized PV accumulation.
// Block = 64 queries, 256 threads (16x16 thread grid, 4q x 4c per thread).
// Key chunks of 64. grid (64, 8).
// ---------------------------------------------------------------------------
__global__ void __launch_bounds__(256) k_attn() {
    __shared__ float th [64][16];
    __shared__ float phT[16][68];              // padded
    __shared__ float gs [64][64];
    __shared__ float P  [64][68];              // padded

    int tid = threadIdx.x;
    int b = blockIdx.y;
    int q0 = blockIdx.x * 64;
    int tq = tid >> 4;                         // 0..15 -> queries [tq*4, tq*4+4)
    int tc = tid & 15;                         // 0..15 -> keys/channels [tc*4, +4)
    int tq4 = tq * 4, tc4 = tc * 4;

    // load theta tile [64][16]
    {
        int row = tid >> 2, j4 = (tid & 3) * 4;
        *(float4*)&th[row][j4] =
            *(const float4*)&g_theta[((size_t)b * N_ + q0 + row) * DQK + j4];
    }
    __syncthreads();
    float thr[4][16];
#pragma unroll
    for (int i = 0; i < 4; i++)
#pragma unroll
        for (int u = 0; u < 4; u++) {
            float4 v = *(const float4*)&th[tq4 + i][u * 4];
            thr[i][u*4+0] = v.x; thr[i][u*4+1] = v.y;
            thr[i][u*4+2] = v.z; thr[i][u*4+3] = v.w;
        }

    // ---------------- Pass 1: row max ----------------
    float mx[4] = {-1e30f, -1e30f, -1e30f, -1e30f};
    for (int c0 = 0; c0 < M_; c0 += 64) {
        __syncthreads();
        {
            int j = tid >> 4, k4 = (tid & 15) * 4;
            *(float4*)&phT[j][k4] =
                *(const float4*)&g_phiT[((size_t)b * DQK + j) * M_ + c0 + k4];
        }
        __syncthreads();
        float s[4][4];
#pragma unroll
        for (int i = 0; i < 4; i++)
#pragma unroll
            for (int k = 0; k < 4; k++) s[i][k] = 0.f;
#pragma unroll
        for (int j = 0; j < 16; j++) {
            float4 pv = *(const float4*)&phT[j][tc4];
#pragma unroll
            for (int i = 0; i < 4; i++) {
                s[i][0] = fmaf(thr[i][j], pv.x, s[i][0]);
                s[i][1] = fmaf(thr[i][j], pv.y, s[i][1]);
                s[i][2] = fmaf(thr[i][j], pv.z, s[i][2]);
                s[i][3] = fmaf(thr[i][j], pv.w, s[i][3]);
            }
        }
#pragma unroll
        for (int i = 0; i < 4; i++)
#pragma unroll
            for (int k = 0; k < 4; k++) mx[i] = fmaxf(mx[i], s[i][k]);
    }
#pragma unroll
    for (int off = 1; off < 16; off <<= 1)
#pragma unroll
        for (int i = 0; i < 4; i++)
            mx[i] = fmaxf(mx[i], __shfl_xor_sync(0xffffffffu, mx[i], off));

    // ---------------- Pass 2: exp + PV GEMM (unnormalized) ----------------
    float z[4] = {0.f, 0.f, 0.f, 0.f};
    float o[4][4];
#pragma unroll
    for (int i = 0; i < 4; i++)
#pragma unroll
        for (int j = 0; j < 4; j++) o[i][j] = 0.f;

    for (int c0 = 0; c0 < M_; c0 += 64) {
        __syncthreads();
        {
            int j = tid >> 4, k4 = (tid & 15) * 4;
            *(float4*)&phT[j][k4] =
                *(const float4*)&g_phiT[((size_t)b * DQK + j) * M_ + c0 + k4];
        }
#pragma unroll
        for (int t = 0; t < 4; t++) {
            int f = t * 256 + tid;
            int r = f >> 4, c4 = (f & 15) * 4;
            *(float4*)&gs[r][c4] =
                *(const float4*)&g_gv[((size_t)b * M_ + c0 + r) * DV + c4];
        }
        __syncthreads();

        float s[4][4];
#pragma unroll
        for (int i = 0; i < 4; i++)
#pragma unroll
            for (int k = 0; k < 4; k++) s[i][k] = 0.f;
#pragma unroll
        for (int j = 0; j < 16; j++) {
            float4 pv = *(const float4*)&phT[j][tc4];
#pragma unroll
            for (int i = 0; i < 4; i++) {
                s[i][0] = fmaf(thr[i][j], pv.x, s[i][0]);
                s[i][1] = fmaf(thr[i][j], pv.y, s[i][1]);
                s[i][2] = fmaf(thr[i][j], pv.z, s[i][2]);
                s[i][3] = fmaf(thr[i][j], pv.w, s[i][3]);
            }
        }
#pragma unroll
        for (int i = 0; i < 4; i++)
#pragma unroll
            for (int k = 0; k < 4; k++) {
                float pe = fast_exp(s[i][k] - mx[i]);
                z[i] += pe;
                P[tq4 + i][tc4 + k] = pe;
            }
        __syncthreads();

#pragma unroll 8
        for (int kk = 0; kk < 64; kk++) {
            float4 gv = *(const float4*)&gs[kk][tc4];
#pragma unroll
            for (int i = 0; i < 4; i++) {
                float pw = P[tq4 + i][kk];
                o[i][0] = fmaf(pw, gv.x, o[i][0]);
                o[i][1] = fmaf(pw, gv.y, o[i][1]);
                o[i][2] = fmaf(pw, gv.z, o[i][2]);
                o[i][3] = fmaf(pw, gv.w, o[i][3]);
            }
        }
    }

    // reduce Z across the 16 tc-threads sharing each query row
#pragma unroll
    for (int off = 1; off < 16; off <<= 1)
#pragma unroll
        for (int i = 0; i < 4; i++)
            z[i] += __shfl_xor_sync(0xffffffffu, z[i], off);

#pragma unroll
    for (int i = 0; i < 4; i++) {
        float inv = 1.0f / z[i];
#pragma unroll
        for (int j = 0; j < 4; j++)
            g_ov[((size_t)b * DV + tc4 + j) * N_ + q0 + tq4 + i] = o[i][j] * inv;
    }
}

// ---------------------------------------------------------------------------
// Kernel 4: out = gamma * (W_o @ o) + x.   grid (16, 4, 8), 256 threads.
// Each block: 256 pixels x 32 output channels.
// ---------------------------------------------------------------------------
__global__ void k_out(const float* __restrict__ x, const float* __restrict__ Wo,
                      const float* __restrict__ gammap, float* __restrict__ out) {
    __shared__ float WoT[64][32];              // [c][ch_local]
    int tid = threadIdx.x;
    int b = blockIdx.z;
    int ch0 = blockIdx.y * 32;
#pragma unroll
    for (int t = 0; t < 8; t++) {
        int e = t * 256 + tid;                 // e = chl*64 + c
        int chl = e >> 6, c = e & 63;
        WoT[c][chl] = Wo[(size_t)(ch0 + chl) * 64 + c];
    }
    __syncthreads();
    float gamma = *gammap;
    int n = blockIdx.x * 256 + tid;

    float acc[32];
#pragma unroll
    for (int i = 0; i < 32; i++) acc[i] = 0.f;
#pragma unroll 2
    for (int c = 0; c < 64; c++) {
        float ov = g_ov[((size_t)b * DV + c) * N_ + n];
#pragma unroll
        for (int u = 0; u < 8; u++) {
            float4 wv = *(const float4*)&WoT[c][u * 4];
            acc[u*4+0] = fmaf(ov, wv.x, acc[u*4+0]);
            acc[u*4+1] = fmaf(ov, wv.y, acc[u*4+1]);
            acc[u*4+2] = fmaf(ov, wv.z, acc[u*4+2]);
            acc[u*4+3] = fmaf(ov, wv.w, acc[u*4+3]);
        }
    }
#pragma unroll
    for (int chl = 0; chl < 32; chl++) {
        size_t idx = ((size_t)b * C_ + ch0 + chl) * N_ + n;
        out[idx] = fmaf(gamma, acc[chl], x[idx]);
    }
}

// ---------------------------------------------------------------------------
extern "C" void kernel_launch(void* const* d_in, const int* in_sizes, int n_in,
                              void* d_out, int out_size) {
    const float* x     = (const float*)d_in[0];   // [8,128,64,64]
    const float* Wth   = (const float*)d_in[1];   // [16,128]
    const float* Wph   = (const float*)d_in[2];   // [16,128]
    const float* Wg    = (const float*)d_in[3];   // [64,128]
    const float* Wo    = (const float*)d_in[4];   // [128,64]
    const float* gamma = (const float*)d_in[5];   // scalar
    float* out = (float*)d_out;

    k_theta<<<dim3(16, 8), 256>>>(x, Wth);
    k_phig <<<dim3(16, 8), 256>>>(x, Wph, Wg);
    k_attn <<<dim3(64, 8), 256>>>();
    k_out  <<<dim3(16, 4, 8), 256>>>(x, Wo, gamma, out);
}

// round 3
// speedup vs baseline: 2.4516x; 2.4516x over previous
#include <cuda_runtime.h>
#include <cuda_bf16.h>
#include <cstdint>

#define B_   8
#define C_   128
#define N_   4096
#define M_   1024
#define DQK  16
#define DV   64

// ---------------- device scratch (allocation-free contract) -----------------
static __device__ __nv_bfloat16 g_theta_bf[B_ * N_ * DQK];   // [b][n][16]
static __device__ __nv_bfloat16 g_phi_bf  [B_ * M_ * DQK];   // [b][m][16]
static __device__ __nv_bfloat16 g_gT      [B_ * DV * M_];    // [b][ch][m]
static __device__ float         g_ov      [B_ * DV * N_];    // [b][ch][n]

// ---------------- helpers ----------------
__device__ __forceinline__ uint32_t smem_u32(const void* p) {
    uint32_t a;
    asm("{ .reg .u64 t; cvta.to.shared.u64 t, %1; cvt.u32.u64 %0, t; }" : "=r"(a) : "l"(p));
    return a;
}
__device__ __forceinline__ void cp16(uint32_t dst, const void* src) {
    asm volatile("cp.async.cg.shared.global [%0], [%1], 16;" :: "r"(dst), "l"(src));
}
#define CP_COMMIT() asm volatile("cp.async.commit_group;" ::: "memory")
#define CP_WAIT(n)  asm volatile("cp.async.wait_group %0;" :: "n"(n) : "memory")

// D += A(16x16,bf16,row) * B(16x8,bf16,col);  D/C in-place fp32
__device__ __forceinline__ void mma_bf16(float d[4], const uint32_t a[4], const uint32_t b[2]) {
    asm volatile("mma.sync.aligned.m16n8k16.row.col.f32.bf16.bf16.f32 "
        "{%0,%1,%2,%3}, {%4,%5,%6,%7}, {%8,%9}, {%0,%1,%2,%3};"
        : "+f"(d[0]), "+f"(d[1]), "+f"(d[2]), "+f"(d[3])
        : "r"(a[0]), "r"(a[1]), "r"(a[2]), "r"(a[3]), "r"(b[0]), "r"(b[1]));
}
__device__ __forceinline__ uint32_t packbf(float lo, float hi) {
    uint32_t r;
    asm("cvt.rn.satfinite.bf16x2.f32 %0, %1, %2;" : "=r"(r) : "f"(hi), "f"(lo));
    return r;
}

// ============================================================================
// Kernel 1: theta = W_theta @ x  -> bf16 [b][n][16].  grid (16,8), 256 thr.
// ============================================================================
__global__ void k_theta(const float* __restrict__ x, const float* __restrict__ Wth) {
    __shared__ float Wt[128][16];
    int tid = threadIdx.x, b = blockIdx.y;
#pragma unroll
    for (int t = 0; t < 8; t++) { int e = t * 256 + tid; Wt[e & 127][e >> 7] = Wth[e]; }
    __syncthreads();
    int n = blockIdx.x * 256 + tid;
    const float* xp = x + ((size_t)b * C_) * N_ + n;
    float acc[16];
#pragma unroll
    for (int i = 0; i < 16; i++) acc[i] = 0.f;
#pragma unroll 4
    for (int c = 0; c < 128; c++) {
        float xv = xp[(size_t)c * N_];
#pragma unroll
        for (int u = 0; u < 4; u++) {
            float4 w = *(const float4*)&Wt[c][u * 4];
            acc[u*4+0] = fmaf(xv, w.x, acc[u*4+0]);
            acc[u*4+1] = fmaf(xv, w.y, acc[u*4+1]);
            acc[u*4+2] = fmaf(xv, w.z, acc[u*4+2]);
            acc[u*4+3] = fmaf(xv, w.w, acc[u*4+3]);
        }
    }
    uint32_t pk[8];
#pragma unroll
    for (int i = 0; i < 8; i++) pk[i] = packbf(acc[2*i], acc[2*i+1]);
    uint4* dst = (uint4*)&g_theta_bf[((size_t)b * N_ + n) * DQK];
    dst[0] = make_uint4(pk[0], pk[1], pk[2], pk[3]);
    dst[1] = make_uint4(pk[4], pk[5], pk[6], pk[7]);
}

// ============================================================================
// Kernel 2: phi (pooled) -> bf16 [b][m][16];  g (pooled) -> bf16 [b][ch][m].
// 8 threads per pooled cell: pix=t&3, half=(t>>2)&1.  grid (32,8), 256 thr.
// ============================================================================
__global__ void __launch_bounds__(256) k_phig(const float* __restrict__ x,
                       const float* __restrict__ Wph, const float* __restrict__ Wg) {
    __shared__ float Wpt[128][16];
    __shared__ float Wgt[128][64];
    int tid = threadIdx.x, b = blockIdx.y;
#pragma unroll
    for (int t = 0; t < 8; t++)  { int e = t * 256 + tid; Wpt[e & 127][e >> 7] = Wph[e]; }
#pragma unroll
    for (int t = 0; t < 32; t++) { int e = t * 256 + tid; Wgt[e & 127][e >> 7] = Wg[e]; }
    __syncthreads();

    int cell = blockIdx.x * 32 + (tid >> 3);
    int pix  = tid & 3, half = (tid >> 2) & 1;
    int ph = cell >> 5, pw = cell & 31;
    int n = (ph * 2 + (pix >> 1)) * 64 + pw * 2 + (pix & 1);
    const float* xp = x + ((size_t)b * C_) * N_ + n;
    int ch0 = half * 32;

    float ap[16], ag[32];
#pragma unroll
    for (int i = 0; i < 16; i++) ap[i] = 0.f;
#pragma unroll
    for (int i = 0; i < 32; i++) ag[i] = 0.f;

#pragma unroll 2
    for (int c = 0; c < 128; c++) {
        float xv = xp[(size_t)c * N_];
#pragma unroll
        for (int u = 0; u < 4; u++) {
            float4 w = *(const float4*)&Wpt[c][u * 4];
            ap[u*4+0] = fmaf(xv, w.x, ap[u*4+0]);
            ap[u*4+1] = fmaf(xv, w.y, ap[u*4+1]);
            ap[u*4+2] = fmaf(xv, w.z, ap[u*4+2]);
            ap[u*4+3] = fmaf(xv, w.w, ap[u*4+3]);
        }
#pragma unroll
        for (int u = 0; u < 8; u++) {
            float4 w = *(const float4*)&Wgt[c][ch0 + u * 4];
            ag[u*4+0] = fmaf(xv, w.x, ag[u*4+0]);
            ag[u*4+1] = fmaf(xv, w.y, ag[u*4+1]);
            ag[u*4+2] = fmaf(xv, w.z, ag[u*4+2]);
            ag[u*4+3] = fmaf(xv, w.w, ag[u*4+3]);
        }
    }
#pragma unroll
    for (int i = 0; i < 16; i++) {
        ap[i] = fmaxf(ap[i], __shfl_xor_sync(0xffffffffu, ap[i], 1));
        ap[i] = fmaxf(ap[i], __shfl_xor_sync(0xffffffffu, ap[i], 2));
    }
#pragma unroll
    for (int i = 0; i < 32; i++) {
        ag[i] = fmaxf(ag[i], __shfl_xor_sync(0xffffffffu, ag[i], 1));
        ag[i] = fmaxf(ag[i], __shfl_xor_sync(0xffffffffu, ag[i], 2));
    }
    if (pix == 0) {
        if (half == 0) {
            uint32_t pk[8];
#pragma unroll
            for (int i = 0; i < 8; i++) pk[i] = packbf(ap[2*i], ap[2*i+1]);
            uint4* dst = (uint4*)&g_phi_bf[((size_t)b * M_ + cell) * DQK];
            dst[0] = make_uint4(pk[0], pk[1], pk[2], pk[3]);
            dst[1] = make_uint4(pk[4], pk[5], pk[6], pk[7]);
        }
#pragma unroll
        for (int i = 0; i < 32; i++)
            g_gT[((size_t)b * DV + ch0 + i) * M_ + cell] = __float2bfloat16(ag[i]);
    }
}

// ============================================================================
// Kernel 3: fused attention with mma.sync bf16 (register accumulators).
// Block = 128 queries, 4 warps (32 q each, two m16 tiles). 8 key-chunks of 128.
// grid (32, 8), 128 threads.
// ============================================================================
__global__ void __launch_bounds__(128) k_attn() {
    __shared__ __align__(16) __nv_bfloat16 s_th[128 * 16];          // 4KB
    __shared__ __align__(16) __nv_bfloat16 s_phi[2][128 * 16];      // 8KB
    __shared__ __align__(16) unsigned char s_big[2][17408];         // gT [64][136]bf16 x2 / osm

    int tid = threadIdx.x, b = blockIdx.y, q0 = blockIdx.x * 128;
    int warp = tid >> 5, lane = tid & 31, g = lane >> 2, t = lane & 3;
    uint32_t th_s  = smem_u32(s_th);
    uint32_t phi_s = smem_u32(s_phi);
    uint32_t big_s = smem_u32(s_big);

    // theta tile -> smem (folded into chunk-0 cp.async group)
    {
        const char* src = (const char*)&g_theta_bf[((size_t)b * N_ + q0) * DQK];
        cp16(th_s + tid * 16,         src + tid * 16);
        cp16(th_s + (tid + 128) * 16, src + (tid + 128) * 16);
    }
    auto issue_chunk = [&](int c, int buf) {
        const char* gsrc = (const char*)&g_gT[((size_t)b * DV) * M_ + c * 128];
#pragma unroll
        for (int r = 0; r < 8; r++) {
            int i = r * 128 + tid;                    // 1024 x 16B
            int ch = i >> 4, off = i & 15;
            cp16(big_s + buf * 17408 + ch * 272 + off * 16,
                 gsrc + (size_t)ch * 2048 + off * 16);
        }
        const char* psrc = (const char*)&g_phi_bf[((size_t)b * M_ + c * 128) * DQK];
        cp16(phi_s + buf * 4096 + tid * 16,         psrc + tid * 16);
        cp16(phi_s + buf * 4096 + (tid + 128) * 16, psrc + (tid + 128) * 16);
    };
    issue_chunk(0, 0); CP_COMMIT();

    uint32_t thA[2][4];
    float o[2][8][4];
#pragma unroll
    for (int m = 0; m < 2; m++)
#pragma unroll
        for (int n = 0; n < 8; n++)
#pragma unroll
            for (int i = 0; i < 4; i++) o[m][n][i] = 0.f;
    float z[2][2] = {{0.f, 0.f}, {0.f, 0.f}};

    for (int c = 0; c < 8; c++) {
        int buf = c & 1;
        if (c < 7) { issue_chunk(c + 1, buf ^ 1); CP_COMMIT(); CP_WAIT(1); }
        else       { CP_WAIT(0); }
        __syncthreads();

        if (c == 0) {
#pragma unroll
            for (int m = 0; m < 2; m++) {
                int row = warp * 32 + m * 16 + g;
                thA[m][0] = *(const uint32_t*)&s_th[row * 16 + 2 * t];
                thA[m][1] = *(const uint32_t*)&s_th[(row + 8) * 16 + 2 * t];
                thA[m][2] = *(const uint32_t*)&s_th[row * 16 + 2 * t + 8];
                thA[m][3] = *(const uint32_t*)&s_th[(row + 8) * 16 + 2 * t + 8];
            }
        }
        const __nv_bfloat16* phis = s_phi[buf];
        const __nv_bfloat16* gts  = (const __nv_bfloat16*)s_big[buf];

#pragma unroll
        for (int kt = 0; kt < 8; kt++) {
            // phi B-fragments for key sub-tiles 2kt, 2kt+1
            uint32_t pb[2][2];
#pragma unroll
            for (int j = 0; j < 2; j++) {
                int key = (2 * kt + j) * 8 + g;
                pb[j][0] = *(const uint32_t*)&phis[key * 16 + 2 * t];
                pb[j][1] = *(const uint32_t*)&phis[key * 16 + 2 * t + 8];
            }
            // S = theta @ phi^T, exp, pack as A-fragment for PV
            uint32_t pa[2][4];
#pragma unroll
            for (int m = 0; m < 2; m++) {
                float s0[4] = {0.f, 0.f, 0.f, 0.f}, s1[4] = {0.f, 0.f, 0.f, 0.f};
                mma_bf16(s0, thA[m], pb[0]);
                mma_bf16(s1, thA[m], pb[1]);
                float e00 = __expf(s0[0]), e01 = __expf(s0[1]);
                float e02 = __expf(s0[2]), e03 = __expf(s0[3]);
                float e10 = __expf(s1[0]), e11 = __expf(s1[1]);
                float e12 = __expf(s1[2]), e13 = __expf(s1[3]);
                z[m][0] += (e00 + e01) + (e10 + e11);
                z[m][1] += (e02 + e03) + (e12 + e13);
                pa[m][0] = packbf(e00, e01); pa[m][1] = packbf(e02, e03);
                pa[m][2] = packbf(e10, e11); pa[m][3] = packbf(e12, e13);
            }
            // O += P @ G   (B-fragments from transposed G tile, stride 136)
#pragma unroll
            for (int n = 0; n < 8; n++) {
                uint32_t gb[2];
                const __nv_bfloat16* gr = &gts[(n * 8 + g) * 136 + kt * 16 + 2 * t];
                gb[0] = *(const uint32_t*)gr;
                gb[1] = *(const uint32_t*)(gr + 8);
                mma_bf16(o[0][n], pa[0], gb);
                mma_bf16(o[1][n], pa[1], gb);
            }
        }
        __syncthreads();
    }

    // z: reduce across the 4 lanes sharing each row
#pragma unroll
    for (int m = 0; m < 2; m++)
#pragma unroll
        for (int h = 0; h < 2; h++) {
            z[m][h] += __shfl_xor_sync(0xffffffffu, z[m][h], 1);
            z[m][h] += __shfl_xor_sync(0xffffffffu, z[m][h], 2);
        }
    float inv[2][2];
#pragma unroll
    for (int m = 0; m < 2; m++) { inv[m][0] = 1.f / z[m][0]; inv[m][1] = 1.f / z[m][1]; }

    // stage O (normalized) via per-warp smem [64ch][34q], then coalesced write
    float* os = (float*)((char*)s_big + warp * 8704);
#pragma unroll
    for (int m = 0; m < 2; m++)
#pragma unroll
        for (int n = 0; n < 8; n++) {
            int ch = n * 8 + 2 * t, qi = m * 16 + g;
            os[ch * 34 + qi]           = o[m][n][0] * inv[m][0];
            os[(ch + 1) * 34 + qi]     = o[m][n][1] * inv[m][0];
            os[ch * 34 + qi + 8]       = o[m][n][2] * inv[m][1];
            os[(ch + 1) * 34 + qi + 8] = o[m][n][3] * inv[m][1];
        }
    __syncwarp();
    float* dst = &g_ov[((size_t)b * DV) * N_ + q0 + warp * 32];
#pragma unroll 4
    for (int ch = 0; ch < 64; ch++)
        dst[(size_t)ch * N_ + lane] = os[ch * 34 + lane];
}

// ============================================================================
// Kernel 4: out = gamma * (W_o @ o) + x.  grid (8,8,8), 256 thr.
// 2 pixels x 16 channels per thread.
// ============================================================================
__global__ void __launch_bounds__(256) k_out(const float* __restrict__ x,
                      const float* __restrict__ Wo,
                      const float* __restrict__ gammap, float* __restrict__ out) {
    __shared__ float WoT[64][16];
    int tid = threadIdx.x;
    int b = blockIdx.z, ch0 = blockIdx.y * 16;
#pragma unroll
    for (int t = 0; t < 4; t++) {
        int e = t * 256 + tid;
        WoT[e & 63][e >> 6] = Wo[(size_t)(ch0 + (e >> 6)) * 64 + (e & 63)];
    }
    __syncthreads();
    float gamma = *gammap;
    int n0 = blockIdx.x * 512 + tid * 2;

    float a0[16], a1[16];
#pragma unroll
    for (int i = 0; i < 16; i++) { a0[i] = 0.f; a1[i] = 0.f; }
#pragma unroll 2
    for (int c = 0; c < 64; c++) {
        float2 ov = *(const float2*)&g_ov[((size_t)b * DV + c) * N_ + n0];
#pragma unroll
        for (int u = 0; u < 4; u++) {
            float4 w = *(const float4*)&WoT[c][u * 4];
            a0[u*4+0] = fmaf(ov.x, w.x, a0[u*4+0]); a1[u*4+0] = fmaf(ov.y, w.x, a1[u*4+0]);
            a0[u*4+1] = fmaf(ov.x, w.y, a0[u*4+1]); a1[u*4+1] = fmaf(ov.y, w.y, a1[u*4+1]);
            a0[u*4+2] = fmaf(ov.x, w.z, a0[u*4+2]); a1[u*4+2] = fmaf(ov.y, w.z, a1[u*4+2]);
            a0[u*4+3] = fmaf(ov.x, w.w, a0[u*4+3]); a1[u*4+3] = fmaf(ov.y, w.w, a1[u*4+3]);
        }
    }
#pragma unroll
    for (int chl = 0; chl < 16; chl++) {
        size_t idx = ((size_t)b * C_ + ch0 + chl) * N_ + n0;
        float2 xv = *(const float2*)&x[idx];
        *(float2*)&out[idx] =
            make_float2(fmaf(gamma, a0[chl], xv.x), fmaf(gamma, a1[chl], xv.y));
    }
}

// ---------------------------------------------------------------------------
extern "C" void kernel_launch(void* const* d_in, const int* in_sizes, int n_in,
                              void* d_out, int out_size) {
    const float* x     = (const float*)d_in[0];
    const float* Wth   = (const float*)d_in[1];
    const float* Wph   = (const float*)d_in[2];
    const float* Wg    = (const float*)d_in[3];
    const float* Wo    = (const float*)d_in[4];
    const float* gamma = (const float*)d_in[5];
    float* out = (float*)d_out;

    k_theta<<<dim3(16, 8), 256>>>(x, Wth);
    k_phig <<<dim3(32, 8), 256>>>(x, Wph, Wg);
    k_attn <<<dim3(32, 8), 128>>>();
    k_out  <<<dim3(8, 8, 8), 256>>>(x, Wo, gamma, out);
}

// round 4
// speedup vs baseline: 2.8705x; 1.1708x over previous
#include <cuda_runtime.h>
#include <cuda_bf16.h>
#include <cstdint>

#define B_   8
#define C_   128
#define N_   4096
#define M_   1024
#define DQK  16
#define DV   64

// ---------------- device scratch ----------------
static __device__ __nv_bfloat16 g_theta_bf[B_ * N_ * DQK];   // [b][n][16]
static __device__ __nv_bfloat16 g_phi_bf  [B_ * M_ * DQK];   // [b][m][16]
static __device__ __nv_bfloat16 g_gT      [B_ * DV * M_];    // [b][ch][m]

// ---------------- helpers ----------------
__device__ __forceinline__ uint32_t smem_u32(const void* p) {
    uint32_t a;
    asm("{ .reg .u64 t; cvta.to.shared.u64 t, %1; cvt.u32.u64 %0, t; }" : "=r"(a) : "l"(p));
    return a;
}
__device__ __forceinline__ void cp16(uint32_t dst, const void* src) {
    asm volatile("cp.async.cg.shared.global [%0], [%1], 16;" :: "r"(dst), "l"(src));
}
#define CP_COMMIT() asm volatile("cp.async.commit_group;" ::: "memory")
#define CP_WAIT(n)  asm volatile("cp.async.wait_group %0;" :: "n"(n) : "memory")

__device__ __forceinline__ void mma_bf16(float d[4], const uint32_t a[4], const uint32_t b[2]) {
    asm volatile("mma.sync.aligned.m16n8k16.row.col.f32.bf16.bf16.f32 "
        "{%0,%1,%2,%3}, {%4,%5,%6,%7}, {%8,%9}, {%0,%1,%2,%3};"
        : "+f"(d[0]), "+f"(d[1]), "+f"(d[2]), "+f"(d[3])
        : "r"(a[0]), "r"(a[1]), "r"(a[2]), "r"(a[3]), "r"(b[0]), "r"(b[1]));
}
__device__ __forceinline__ uint32_t packbf(float lo, float hi) {
    uint32_t r;
    asm("cvt.rn.satfinite.bf16x2.f32 %0, %1, %2;" : "=r"(r) : "f"(hi), "f"(lo));
    return r;
}

// ============================================================================
// Kernel 1: merged projections.  grid (48, 8), 256 thr.
//   bx <  16 : theta = W_theta @ x  -> bf16 [b][n][16]
//   bx >= 16 : phi (pooled) -> bf16 [b][m][16];  g (pooled) -> bf16 [b][ch][m]
// ============================================================================
__global__ void __launch_bounds__(256) k_proj(const float* __restrict__ x,
                       const float* __restrict__ Wth,
                       const float* __restrict__ Wph, const float* __restrict__ Wg) {
    __shared__ float Wa[128][16];
    __shared__ float Wb[128][64];
    int tid = threadIdx.x, b = blockIdx.y;

    if (blockIdx.x < 16) {
        // ---------------- theta role ----------------
#pragma unroll
        for (int t = 0; t < 8; t++) { int e = t * 256 + tid; Wa[e & 127][e >> 7] = Wth[e]; }
        __syncthreads();
        int n = blockIdx.x * 256 + tid;
        const float* xp = x + ((size_t)b * C_) * N_ + n;
        float acc[16];
#pragma unroll
        for (int i = 0; i < 16; i++) acc[i] = 0.f;
#pragma unroll 4
        for (int c = 0; c < 128; c++) {
            float xv = xp[(size_t)c * N_];
#pragma unroll
            for (int u = 0; u < 4; u++) {
                float4 w = *(const float4*)&Wa[c][u * 4];
                acc[u*4+0] = fmaf(xv, w.x, acc[u*4+0]);
                acc[u*4+1] = fmaf(xv, w.y, acc[u*4+1]);
                acc[u*4+2] = fmaf(xv, w.z, acc[u*4+2]);
                acc[u*4+3] = fmaf(xv, w.w, acc[u*4+3]);
            }
        }
        uint32_t pk[8];
#pragma unroll
        for (int i = 0; i < 8; i++) pk[i] = packbf(acc[2*i], acc[2*i+1]);
        uint4* dst = (uint4*)&g_theta_bf[((size_t)b * N_ + n) * DQK];
        dst[0] = make_uint4(pk[0], pk[1], pk[2], pk[3]);
        dst[1] = make_uint4(pk[4], pk[5], pk[6], pk[7]);
        return;
    }

    // ---------------- phi + g role ----------------
#pragma unroll
    for (int t = 0; t < 8; t++)  { int e = t * 256 + tid; Wa[e & 127][e >> 7] = Wph[e]; }
#pragma unroll
    for (int t = 0; t < 32; t++) { int e = t * 256 + tid; Wb[e & 127][e >> 7] = Wg[e]; }
    __syncthreads();

    int cell = (blockIdx.x - 16) * 32 + (tid >> 3);
    int pix  = tid & 3, half = (tid >> 2) & 1;
    int ph = cell >> 5, pw = cell & 31;
    int n = (ph * 2 + (pix >> 1)) * 64 + pw * 2 + (pix & 1);
    const float* xp = x + ((size_t)b * C_) * N_ + n;
    int ch0 = half * 32;

    float ap[16], ag[32];
#pragma unroll
    for (int i = 0; i < 16; i++) ap[i] = 0.f;
#pragma unroll
    for (int i = 0; i < 32; i++) ag[i] = 0.f;

#pragma unroll 2
    for (int c = 0; c < 128; c++) {
        float xv = xp[(size_t)c * N_];
#pragma unroll
        for (int u = 0; u < 4; u++) {
            float4 w = *(const float4*)&Wa[c][u * 4];
            ap[u*4+0] = fmaf(xv, w.x, ap[u*4+0]);
            ap[u*4+1] = fmaf(xv, w.y, ap[u*4+1]);
            ap[u*4+2] = fmaf(xv, w.z, ap[u*4+2]);
            ap[u*4+3] = fmaf(xv, w.w, ap[u*4+3]);
        }
#pragma unroll
        for (int u = 0; u < 8; u++) {
            float4 w = *(const float4*)&Wb[c][ch0 + u * 4];
            ag[u*4+0] = fmaf(xv, w.x, ag[u*4+0]);
            ag[u*4+1] = fmaf(xv, w.y, ag[u*4+1]);
            ag[u*4+2] = fmaf(xv, w.z, ag[u*4+2]);
            ag[u*4+3] = fmaf(xv, w.w, ag[u*4+3]);
        }
    }
#pragma unroll
    for (int i = 0; i < 16; i++) {
        ap[i] = fmaxf(ap[i], __shfl_xor_sync(0xffffffffu, ap[i], 1));
        ap[i] = fmaxf(ap[i], __shfl_xor_sync(0xffffffffu, ap[i], 2));
    }
#pragma unroll
    for (int i = 0; i < 32; i++) {
        ag[i] = fmaxf(ag[i], __shfl_xor_sync(0xffffffffu, ag[i], 1));
        ag[i] = fmaxf(ag[i], __shfl_xor_sync(0xffffffffu, ag[i], 2));
    }
    if (pix == 0) {
        if (half == 0) {
            uint32_t pk[8];
#pragma unroll
            for (int i = 0; i < 8; i++) pk[i] = packbf(ap[2*i], ap[2*i+1]);
            uint4* dst = (uint4*)&g_phi_bf[((size_t)b * M_ + cell) * DQK];
            dst[0] = make_uint4(pk[0], pk[1], pk[2], pk[3]);
            dst[1] = make_uint4(pk[4], pk[5], pk[6], pk[7]);
        }
#pragma unroll
        for (int i = 0; i < 32; i++)
            g_gT[((size_t)b * DV + ch0 + i) * M_ + cell] = __float2bfloat16(ag[i]);
    }
}

// ============================================================================
// Kernel 2: fused attention + W_o + residual.
// Block = 128 queries, 4 warps. 8 key-chunks of 128. grid (32, 8).
// Dynamic smem layout (bytes):
//   [0, 4K)       theta tile            (epilogue: staging overlay, 64x132 fp32)
//   [4K, 12K)     phi double buffer
//   [12K, 46.75K) gT double buffer (2 x 17408: [64ch][136bf16])
//   [46.75K, 64K) Wo bf16 [128outch][68]
// ============================================================================
#define TH_OFF   0
#define PHI_OFF  4096
#define BIG_OFF  12288
#define WO_OFF   47104
#define SMEM_ATTN 64512

__global__ void __launch_bounds__(128) k_attn(const float* __restrict__ x,
                      const float* __restrict__ Wo,
                      const float* __restrict__ gammap, float* __restrict__ out) {
    extern __shared__ __align__(16) unsigned char smem[];
    int tid = threadIdx.x, b = blockIdx.y, q0 = blockIdx.x * 128;
    int warp = tid >> 5, lane = tid & 31, g = lane >> 2, t = lane & 3;
    uint32_t sb = smem_u32(smem);

    // theta tile -> smem
    {
        const char* src = (const char*)&g_theta_bf[((size_t)b * N_ + q0) * DQK];
        cp16(sb + TH_OFF + tid * 16,         src + tid * 16);
        cp16(sb + TH_OFF + (tid + 128) * 16, src + (tid + 128) * 16);
    }
    auto issue_chunk = [&](int c, int buf) {
        const char* gsrc = (const char*)&g_gT[((size_t)b * DV) * M_ + c * 128];
        uint32_t gdst = sb + BIG_OFF + buf * 17408;
#pragma unroll
        for (int r = 0; r < 8; r++) {
            int i = r * 128 + tid;
            int ch = i >> 4, off = i & 15;
            cp16(gdst + ch * 272 + off * 16, gsrc + (size_t)ch * 2048 + off * 16);
        }
        const char* psrc = (const char*)&g_phi_bf[((size_t)b * M_ + c * 128) * DQK];
        cp16(sb + PHI_OFF + buf * 4096 + tid * 16,         psrc + tid * 16);
        cp16(sb + PHI_OFF + buf * 4096 + (tid + 128) * 16, psrc + (tid + 128) * 16);
    };
    issue_chunk(0, 0); CP_COMMIT();

    uint32_t thA[2][4];
    float o[2][8][4];
#pragma unroll
    for (int m = 0; m < 2; m++)
#pragma unroll
        for (int n = 0; n < 8; n++)
#pragma unroll
            for (int i = 0; i < 4; i++) o[m][n][i] = 0.f;
    float z[2][2] = {{0.f, 0.f}, {0.f, 0.f}};

    for (int c = 0; c < 8; c++) {
        int buf = c & 1;
        if (c < 7) { issue_chunk(c + 1, buf ^ 1); CP_COMMIT(); CP_WAIT(1); }
        else       { CP_WAIT(0); }
        __syncthreads();

        const __nv_bfloat16* ths  = (const __nv_bfloat16*)(smem + TH_OFF);
        if (c == 0) {
#pragma unroll
            for (int m = 0; m < 2; m++) {
                int row = warp * 32 + m * 16 + g;
                thA[m][0] = *(const uint32_t*)&ths[row * 16 + 2 * t];
                thA[m][1] = *(const uint32_t*)&ths[(row + 8) * 16 + 2 * t];
                thA[m][2] = *(const uint32_t*)&ths[row * 16 + 2 * t + 8];
                thA[m][3] = *(const uint32_t*)&ths[(row + 8) * 16 + 2 * t + 8];
            }
        }
        const __nv_bfloat16* phis = (const __nv_bfloat16*)(smem + PHI_OFF + buf * 4096);
        const __nv_bfloat16* gts  = (const __nv_bfloat16*)(smem + BIG_OFF + buf * 17408);

#pragma unroll
        for (int kt = 0; kt < 8; kt++) {
            uint32_t pb[2][2];
#pragma unroll
            for (int j = 0; j < 2; j++) {
                int key = (2 * kt + j) * 8 + g;
                pb[j][0] = *(const uint32_t*)&phis[key * 16 + 2 * t];
                pb[j][1] = *(const uint32_t*)&phis[key * 16 + 2 * t + 8];
            }
            uint32_t pa[2][4];
#pragma unroll
            for (int m = 0; m < 2; m++) {
                float s0[4] = {0.f, 0.f, 0.f, 0.f}, s1[4] = {0.f, 0.f, 0.f, 0.f};
                mma_bf16(s0, thA[m], pb[0]);
                mma_bf16(s1, thA[m], pb[1]);
                float e00 = __expf(s0[0]), e01 = __expf(s0[1]);
                float e02 = __expf(s0[2]), e03 = __expf(s0[3]);
                float e10 = __expf(s1[0]), e11 = __expf(s1[1]);
                float e12 = __expf(s1[2]), e13 = __expf(s1[3]);
                z[m][0] += (e00 + e01) + (e10 + e11);
                z[m][1] += (e02 + e03) + (e12 + e13);
                pa[m][0] = packbf(e00, e01); pa[m][1] = packbf(e02, e03);
                pa[m][2] = packbf(e10, e11); pa[m][3] = packbf(e12, e13);
            }
#pragma unroll
            for (int n = 0; n < 8; n++) {
                uint32_t gb[2];
                const __nv_bfloat16* gr = &gts[(n * 8 + g) * 136 + kt * 16 + 2 * t];
                gb[0] = *(const uint32_t*)gr;
                gb[1] = *(const uint32_t*)(gr + 8);
                mma_bf16(o[0][n], pa[0], gb);
                mma_bf16(o[1][n], pa[1], gb);
            }
        }
        __syncthreads();
    }

    // ---------------- epilogue: z-normalize, W_o GEMM, residual ----------------
#pragma unroll
    for (int m = 0; m < 2; m++)
#pragma unroll
        for (int h = 0; h < 2; h++) {
            z[m][h] += __shfl_xor_sync(0xffffffffu, z[m][h], 1);
            z[m][h] += __shfl_xor_sync(0xffffffffu, z[m][h], 2);
        }
    float inv[2][2];
#pragma unroll
    for (int m = 0; m < 2; m++) { inv[m][0] = 1.f / z[m][0]; inv[m][1] = 1.f / z[m][1]; }

    // Wo -> smem bf16 [128][68], row stride 34 words
    {
        uint32_t* wo32 = (uint32_t*)(smem + WO_OFF);
        const float2* wsrc = (const float2*)(Wo + (size_t)tid * 64);
#pragma unroll 8
        for (int j = 0; j < 32; j++) {
            float2 v = wsrc[j];
            wo32[tid * 34 + j] = packbf(v.x, v.y);
        }
    }
    // normalized O -> bf16 A-fragments over inch (k = 4 chunks of 16)
    uint32_t pA[2][4][4];
#pragma unroll
    for (int m = 0; m < 2; m++)
#pragma unroll
        for (int kt = 0; kt < 4; kt++) {
            pA[m][kt][0] = packbf(o[m][2*kt][0]   * inv[m][0], o[m][2*kt][1]   * inv[m][0]);
            pA[m][kt][1] = packbf(o[m][2*kt][2]   * inv[m][1], o[m][2*kt][3]   * inv[m][1]);
            pA[m][kt][2] = packbf(o[m][2*kt+1][0] * inv[m][0], o[m][2*kt+1][1] * inv[m][0]);
            pA[m][kt][3] = packbf(o[m][2*kt+1][2] * inv[m][1], o[m][2*kt+1][3] * inv[m][1]);
        }
    float gamma = *gammap;
    __syncthreads();   // Wo visible; main-loop smem dead

    const uint32_t* wo32 = (const uint32_t*)(smem + WO_OFF);
    float* st = (float*)smem;          // staging overlay [64ch][132]

#pragma unroll
    for (int h = 0; h < 2; h++) {
        float acc[2][8][4];
#pragma unroll
        for (int m = 0; m < 2; m++)
#pragma unroll
            for (int nb = 0; nb < 8; nb++)
#pragma unroll
                for (int i = 0; i < 4; i++) acc[m][nb][i] = 0.f;
#pragma unroll
        for (int nb = 0; nb < 8; nb++) {
            int row = (h * 8 + nb) * 8 + g;          // outch
#pragma unroll
            for (int kt = 0; kt < 4; kt++) {
                uint32_t gb[2];
                gb[0] = wo32[row * 34 + kt * 8 + t];
                gb[1] = wo32[row * 34 + kt * 8 + t + 4];
                mma_bf16(acc[0][nb], pA[0][kt], gb);
                mma_bf16(acc[1][nb], pA[1][kt], gb);
            }
        }
        __syncthreads();   // staging area free (prev iter's reads done)
#pragma unroll
        for (int m = 0; m < 2; m++)
#pragma unroll
            for (int nb = 0; nb < 8; nb++) {
                int ch = nb * 8 + 2 * t, q = warp * 32 + m * 16 + g;
                st[ch * 132 + q]           = acc[m][nb][0];
                st[(ch + 1) * 132 + q]     = acc[m][nb][1];
                st[ch * 132 + q + 8]       = acc[m][nb][2];
                st[(ch + 1) * 132 + q + 8] = acc[m][nb][3];
            }
        __syncthreads();
        const float* xs = x + ((size_t)b * C_ + h * 64) * N_ + q0;
        float* op = out + ((size_t)b * C_ + h * 64) * N_ + q0;
#pragma unroll
        for (int i = 0; i < 16; i++) {
            int e = i * 128 + tid;
            int ch = e >> 5, q4 = (e & 31) * 4;
            float4 v = *(const float4*)&st[ch * 132 + q4];
            float4 xv = *(const float4*)&xs[(size_t)ch * N_ + q4];
            v.x = fmaf(gamma, v.x, xv.x); v.y = fmaf(gamma, v.y, xv.y);
            v.z = fmaf(gamma, v.z, xv.z); v.w = fmaf(gamma, v.w, xv.w);
            *(float4*)&op[(size_t)ch * N_ + q4] = v;
        }
    }
}

// ---------------------------------------------------------------------------
extern "C" void kernel_launch(void* const* d_in, const int* in_sizes, int n_in,
                              void* d_out, int out_size) {
    const float* x     = (const float*)d_in[0];
    const float* Wth   = (const float*)d_in[1];
    const float* Wph   = (const float*)d_in[2];
    const float* Wg    = (const float*)d_in[3];
    const float* Wo    = (const float*)d_in[4];
    const float* gamma = (const float*)d_in[5];
    float* out = (float*)d_out;

    static int configured = 0;
    if (!configured) {
        cudaFuncSetAttribute(k_attn, cudaFuncAttributeMaxDynamicSharedMemorySize, SMEM_ATTN);
        configured = 1;
    }

    k_proj<<<dim3(48, 8), 256>>>(x, Wth, Wph, Wg);
    k_attn<<<dim3(32, 8), 128, SMEM_ATTN>>>(x, Wo, gamma, out);
}

// round 5
// speedup vs baseline: 6.6177x; 2.3054x over previous
#include <cuda_runtime.h>
#include <cuda_bf16.h>
#include <cstdint>

#define B_   8
#define C_   128
#define N_   4096
#define M_   1024
#define DQK  16
#define DV   64

// ---------------- device scratch ----------------
static __device__ __nv_bfloat16 g_theta_bf[B_ * N_ * DQK];   // [b][n][16]
static __device__ __nv_bfloat16 g_phi_bf  [B_ * M_ * DQK];   // [b][m][16]
static __device__ __nv_bfloat16 g_gT      [B_ * DV * M_];    // [b][ch][m]

// ---------------- helpers ----------------
__device__ __forceinline__ uint32_t smem_u32(const void* p) {
    uint32_t a;
    asm("{ .reg .u64 t; cvta.to.shared.u64 t, %1; cvt.u32.u64 %0, t; }" : "=r"(a) : "l"(p));
    return a;
}
__device__ __forceinline__ void cp16(uint32_t dst, const void* src) {
    asm volatile("cp.async.cg.shared.global [%0], [%1], 16;" :: "r"(dst), "l"(src));
}
#define CP_COMMIT() asm volatile("cp.async.commit_group;" ::: "memory")
#define CP_WAIT(n)  asm volatile("cp.async.wait_group %0;" :: "n"(n) : "memory")

__device__ __forceinline__ void mma_bf16(float d[4], const uint32_t a[4], const uint32_t b[2]) {
    asm volatile("mma.sync.aligned.m16n8k16.row.col.f32.bf16.bf16.f32 "
        "{%0,%1,%2,%3}, {%4,%5,%6,%7}, {%8,%9}, {%0,%1,%2,%3};"
        : "+f"(d[0]), "+f"(d[1]), "+f"(d[2]), "+f"(d[3])
        : "r"(a[0]), "r"(a[1]), "r"(a[2]), "r"(a[3]), "r"(b[0]), "r"(b[1]));
}
__device__ __forceinline__ uint32_t packbf(float lo, float hi) {
    uint32_t r;
    asm("cvt.rn.satfinite.bf16x2.f32 %0, %1, %2;" : "=r"(r) : "f"(hi), "f"(lo));
    return r;
}
__device__ __forceinline__ void ldsm_x4(uint32_t r[4], uint32_t addr) {
    asm volatile("ldmatrix.sync.aligned.m8n8.x4.shared.b16 {%0,%1,%2,%3}, [%4];"
        : "=r"(r[0]), "=r"(r[1]), "=r"(r[2]), "=r"(r[3]) : "r"(addr));
}
__device__ __forceinline__ void ldsm_x2t(uint32_t r[2], uint32_t addr) {
    asm volatile("ldmatrix.sync.aligned.m8n8.x2.trans.shared.b16 {%0,%1}, [%2];"
        : "=r"(r[0]), "=r"(r[1]) : "r"(addr));
}

// ============================================================================
// Kernel 1: all projections as one bf16 tensor-core GEMM + fused 2x2 pooling.
// Block = 128 px (2 image rows), 256 thr (8 warps), grid (32, 8).
// A = [96 outch][128 inch] (theta 0..15 | phi 16..31 | g 32..95), B = x tile.
// smem: xs bf16 [128ch][136px] @0 (34816B), ws bf16 [96][136] @34816 (26112B)
// ============================================================================
#define PROJ_WS   34816
#define SMEM_PROJ 60928

__global__ void __launch_bounds__(256) k_proj(const float* __restrict__ x,
                       const float* __restrict__ Wth,
                       const float* __restrict__ Wph, const float* __restrict__ Wg) {
    extern __shared__ __align__(16) unsigned char smem[];
    __nv_bfloat16* xs = (__nv_bfloat16*)smem;               // [128][136]
    __nv_bfloat16* ws = (__nv_bfloat16*)(smem + PROJ_WS);   // [96][136]
    int tid = threadIdx.x, b = blockIdx.y, bx = blockIdx.x;
    int n0 = bx * 128;

    // weights -> smem bf16
#pragma unroll
    for (int k = 0; k < 12; k++) {
        int e = k * 256 + tid;                 // 3072 float4
        int row = e >> 5, c4 = e & 31;
        const float* src = (row < 16) ? &Wth[row * 128]
                         : (row < 32) ? &Wph[(row - 16) * 128]
                                      : &Wg[(row - 32) * 128];
        float4 v = *(const float4*)&src[c4 * 4];
        uint32_t* d = (uint32_t*)&ws[row * 136 + c4 * 4];
        d[0] = packbf(v.x, v.y); d[1] = packbf(v.z, v.w);
    }
    // x tile -> smem bf16 [ch][px]
    const float* xp = x + ((size_t)b * C_) * N_ + n0;
#pragma unroll
    for (int k = 0; k < 16; k++) {
        int e = k * 256 + tid;                 // 4096 float4
        int ch = e >> 5, p4 = e & 31;
        float4 v = *(const float4*)&xp[(size_t)ch * N_ + p4 * 4];
        uint32_t* d = (uint32_t*)&xs[ch * 136 + p4 * 4];
        d[0] = packbf(v.x, v.y); d[1] = packbf(v.z, v.w);
    }
    __syncthreads();

    int warp = tid >> 5, lane = tid & 31, g = lane >> 2, t = lane & 3;
    int px0 = warp * 16;
    // ldmatrix lane addressing
    int aq = lane >> 3;
    int ar = (aq & 1) * 8 + (lane & 7), ac = (aq >> 1) * 8;   // A: row/col within tile
    int bl = lane & 15;                                       // B trans: k row

    float acc[6][2][4];
#pragma unroll
    for (int mi = 0; mi < 6; mi++)
#pragma unroll
        for (int ni = 0; ni < 2; ni++)
#pragma unroll
            for (int i = 0; i < 4; i++) acc[mi][ni][i] = 0.f;

#pragma unroll
    for (int k0 = 0; k0 < 128; k0 += 16) {
        uint32_t bf[2][2];
#pragma unroll
        for (int ni = 0; ni < 2; ni++)
            ldsm_x2t(bf[ni], smem_u32(&xs[(k0 + bl) * 136 + px0 + ni * 8]));
#pragma unroll
        for (int mi = 0; mi < 6; mi++) {
            uint32_t af[4];
            ldsm_x4(af, smem_u32(&ws[(mi * 16 + ar) * 136 + k0 + ac]));
            mma_bf16(acc[mi][0], af, bf[0]);
            mma_bf16(acc[mi][1], af, bf[1]);
        }
    }

    // ---- theta (mi=0): direct scattered stores, [n][16] layout ----
#pragma unroll
    for (int ni = 0; ni < 2; ni++) {
        int px = px0 + ni * 8 + 2 * t;
        __nv_bfloat16* base = &g_theta_bf[((size_t)b * N_ + n0 + px) * DQK];
        base[g]      = __float2bfloat16(acc[0][ni][0]);
        base[16 + g] = __float2bfloat16(acc[0][ni][1]);      // px+1 row
        base[g + 8]      = __float2bfloat16(acc[0][ni][2]);
        base[16 + g + 8] = __float2bfloat16(acc[0][ni][3]);
    }

    // ---- phi/g (mi 1..5): stage bf16 [80][136] over xs, then 2x2 pool ----
    __syncthreads();                       // xs dead for everyone
    __nv_bfloat16* st = xs;                // rows = outch-16
#pragma unroll
    for (int mi = 1; mi < 6; mi++)
#pragma unroll
        for (int ni = 0; ni < 2; ni++) {
            int ro = mi * 16 - 16, pxx = px0 + ni * 8 + 2 * t;
            *(uint32_t*)&st[(ro + g) * 136 + pxx]     = packbf(acc[mi][ni][0], acc[mi][ni][1]);
            *(uint32_t*)&st[(ro + g + 8) * 136 + pxx] = packbf(acc[mi][ni][2], acc[mi][ni][3]);
        }
    __syncthreads();

    int cell0 = bx * 32;
#pragma unroll
    for (int k = 0; k < 10; k++) {
        int e = k * 256 + tid;             // 2560 = 80 outch x 32 quads
        int o = e >> 5, q = e & 31;
        __nv_bfloat162 v0 = *(__nv_bfloat162*)&st[o * 136 + 2 * q];
        __nv_bfloat162 v1 = *(__nv_bfloat162*)&st[o * 136 + 64 + 2 * q];
        float m = fmaxf(fmaxf(__low2float(v0), __high2float(v0)),
                        fmaxf(__low2float(v1), __high2float(v1)));
        if (o < 16)
            g_phi_bf[((size_t)b * M_ + cell0 + q) * DQK + o] = __float2bfloat16(m);
        else
            g_gT[((size_t)b * DV + (o - 16)) * M_ + cell0 + q] = __float2bfloat16(m);
    }
}

// ============================================================================
// Kernel 2: fused attention + W_o + residual.  8 warps x 16 queries.
// Block = 128 queries, 256 threads. 8 key-chunks of 128. grid (32, 8).
// smem: [0,4K) theta | [4K,12K) phi x2 | [12K,46.75K) gT x2 | [46.75K,64K) Wo
//       epilogue overlay: [0, 33792) fp32 staging [64ch][132]
// ============================================================================
#define TH_OFF   0
#define PHI_OFF  4096
#define BIG_OFF  12288
#define WO_OFF   47104
#define SMEM_ATTN 64512

__global__ void __launch_bounds__(256) k_attn(const float* __restrict__ x,
                      const float* __restrict__ Wo,
                      const float* __restrict__ gammap, float* __restrict__ out) {
    extern __shared__ __align__(16) unsigned char smem[];
    int tid = threadIdx.x, b = blockIdx.y, q0 = blockIdx.x * 128;
    int warp = tid >> 5, lane = tid & 31, g = lane >> 2, t = lane & 3;
    uint32_t sb = smem_u32(smem);

    // theta tile -> smem (256 x 16B = 4KB)
    cp16(sb + TH_OFF + tid * 16,
         (const char*)&g_theta_bf[((size_t)b * N_ + q0) * DQK] + tid * 16);
    auto issue_chunk = [&](int c, int buf) {
        const char* gsrc = (const char*)&g_gT[((size_t)b * DV) * M_ + c * 128];
        uint32_t gdst = sb + BIG_OFF + buf * 17408;
#pragma unroll
        for (int r = 0; r < 4; r++) {
            int i = r * 256 + tid;             // 1024 x 16B
            int ch = i >> 4, off = i & 15;
            cp16(gdst + ch * 272 + off * 16, gsrc + (size_t)ch * 2048 + off * 16);
        }
        cp16(sb + PHI_OFF + buf * 4096 + tid * 16,
             (const char*)&g_phi_bf[((size_t)b * M_ + c * 128) * DQK] + tid * 16);
    };
    issue_chunk(0, 0); CP_COMMIT();

    uint32_t thA[4];
    float o[8][4];
#pragma unroll
    for (int n = 0; n < 8; n++)
#pragma unroll
        for (int i = 0; i < 4; i++) o[n][i] = 0.f;
    float z[2] = {0.f, 0.f};

    for (int c = 0; c < 8; c++) {
        int buf = c & 1;
        if (c < 7) { issue_chunk(c + 1, buf ^ 1); CP_COMMIT(); CP_WAIT(1); }
        else       { CP_WAIT(0); }
        __syncthreads();

        if (c == 0) {
            const __nv_bfloat16* ths = (const __nv_bfloat16*)(smem + TH_OFF);
            int row = warp * 16 + g;
            thA[0] = *(const uint32_t*)&ths[row * 16 + 2 * t];
            thA[1] = *(const uint32_t*)&ths[(row + 8) * 16 + 2 * t];
            thA[2] = *(const uint32_t*)&ths[row * 16 + 2 * t + 8];
            thA[3] = *(const uint32_t*)&ths[(row + 8) * 16 + 2 * t + 8];
        }
        const __nv_bfloat16* phis = (const __nv_bfloat16*)(smem + PHI_OFF + buf * 4096);
        const __nv_bfloat16* gts  = (const __nv_bfloat16*)(smem + BIG_OFF + buf * 17408);

#pragma unroll
        for (int kt = 0; kt < 8; kt++) {
            uint32_t pb[2][2];
#pragma unroll
            for (int j = 0; j < 2; j++) {
                int key = (2 * kt + j) * 8 + g;
                pb[j][0] = *(const uint32_t*)&phis[key * 16 + 2 * t];
                pb[j][1] = *(const uint32_t*)&phis[key * 16 + 2 * t + 8];
            }
            float s0[4] = {0.f, 0.f, 0.f, 0.f}, s1[4] = {0.f, 0.f, 0.f, 0.f};
            mma_bf16(s0, thA, pb[0]);
            mma_bf16(s1, thA, pb[1]);
            float e00 = __expf(s0[0]), e01 = __expf(s0[1]);
            float e02 = __expf(s0[2]), e03 = __expf(s0[3]);
            float e10 = __expf(s1[0]), e11 = __expf(s1[1]);
            float e12 = __expf(s1[2]), e13 = __expf(s1[3]);
            z[0] += (e00 + e01) + (e10 + e11);
            z[1] += (e02 + e03) + (e12 + e13);
            uint32_t pa[4];
            pa[0] = packbf(e00, e01); pa[1] = packbf(e02, e03);
            pa[2] = packbf(e10, e11); pa[3] = packbf(e12, e13);
#pragma unroll
            for (int n = 0; n < 8; n++) {
                uint32_t gb[2];
                const __nv_bfloat16* gr = &gts[(n * 8 + g) * 136 + kt * 16 + 2 * t];
                gb[0] = *(const uint32_t*)gr;
                gb[1] = *(const uint32_t*)(gr + 8);
                mma_bf16(o[n], pa, gb);
            }
        }
        __syncthreads();
    }

    // ---------------- epilogue: normalize, W_o GEMM, residual ----------------
    z[0] += __shfl_xor_sync(0xffffffffu, z[0], 1);
    z[0] += __shfl_xor_sync(0xffffffffu, z[0], 2);
    z[1] += __shfl_xor_sync(0xffffffffu, z[1], 1);
    z[1] += __shfl_xor_sync(0xffffffffu, z[1], 2);
    float inv0 = 1.f / z[0], inv1 = 1.f / z[1];

    // Wo -> smem bf16 [128][68]
    {
        uint32_t* wo32 = (uint32_t*)(smem + WO_OFF);
        int row = tid >> 1, half = tid & 1;
        const float2* wsrc = (const float2*)(Wo + (size_t)row * 64) + half * 16;
#pragma unroll
        for (int j = 0; j < 16; j++) {
            float2 v = wsrc[j];
            wo32[row * 34 + half * 16 + j] = packbf(v.x, v.y);
        }
    }
    // normalized O -> bf16 A-fragments (k = 4 chunks of 16 inch)
    uint32_t pA[4][4];
#pragma unroll
    for (int kt = 0; kt < 4; kt++) {
        pA[kt][0] = packbf(o[2*kt][0]   * inv0, o[2*kt][1]   * inv0);
        pA[kt][1] = packbf(o[2*kt][2]   * inv1, o[2*kt][3]   * inv1);
        pA[kt][2] = packbf(o[2*kt+1][0] * inv0, o[2*kt+1][1] * inv0);
        pA[kt][3] = packbf(o[2*kt+1][2] * inv1, o[2*kt+1][3] * inv1);
    }
    float gamma = *gammap;
    __syncthreads();

    const uint32_t* wo32 = (const uint32_t*)(smem + WO_OFF);
    float* st = (float*)smem;              // [64ch][132]

#pragma unroll
    for (int h = 0; h < 2; h++) {
        float acc[8][4];
#pragma unroll
        for (int nb = 0; nb < 8; nb++)
#pragma unroll
            for (int i = 0; i < 4; i++) acc[nb][i] = 0.f;
#pragma unroll
        for (int nb = 0; nb < 8; nb++) {
            int row = (h * 8 + nb) * 8 + g;
#pragma unroll
            for (int kt = 0; kt < 4; kt++) {
                uint32_t gb[2];
                gb[0] = wo32[row * 34 + kt * 8 + t];
                gb[1] = wo32[row * 34 + kt * 8 + t + 4];
                mma_bf16(acc[nb], pA[kt], gb);
            }
        }
        __syncthreads();
#pragma unroll
        for (int nb = 0; nb < 8; nb++) {
            int ch = nb * 8 + 2 * t, q = warp * 16 + g;
            st[ch * 132 + q]           = acc[nb][0];
            st[(ch + 1) * 132 + q]     = acc[nb][1];
            st[ch * 132 + q + 8]       = acc[nb][2];
            st[(ch + 1) * 132 + q + 8] = acc[nb][3];
        }
        __syncthreads();
        const float* xs = x + ((size_t)b * C_ + h * 64) * N_ + q0;
        float* op = out + ((size_t)b * C_ + h * 64) * N_ + q0;
#pragma unroll
        for (int i = 0; i < 8; i++) {
            int e = i * 256 + tid;
            int ch = e >> 5, q4 = (e & 31) * 4;
            float4 v = *(const float4*)&st[ch * 132 + q4];
            float4 xv = *(const float4*)&xs[(size_t)ch * N_ + q4];
            v.x = fmaf(gamma, v.x, xv.x); v.y = fmaf(gamma, v.y, xv.y);
            v.z = fmaf(gamma, v.z, xv.z); v.w = fmaf(gamma, v.w, xv.w);
            *(float4*)&op[(size_t)ch * N_ + q4] = v;
        }
    }
}

// ---------------------------------------------------------------------------
extern "C" void kernel_launch(void* const* d_in, const int* in_sizes, int n_in,
                              void* d_out, int out_size) {
    const float* x     = (const float*)d_in[0];
    const float* Wth   = (const float*)d_in[1];
    const float* Wph   = (const float*)d_in[2];
    const float* Wg    = (const float*)d_in[3];
    const float* Wo    = (const float*)d_in[4];
    const float* gamma = (const float*)d_in[5];
    float* out = (float*)d_out;

    static int configured = 0;
    if (!configured) {
        cudaFuncSetAttribute(k_proj, cudaFuncAttributeMaxDynamicSharedMemorySize, SMEM_PROJ);
        cudaFuncSetAttribute(k_attn, cudaFuncAttributeMaxDynamicSharedMemorySize, SMEM_ATTN);
        configured = 1;
    }

    k_proj<<<dim3(32, 8), 256, SMEM_PROJ>>>(x, Wth, Wph, Wg);
    k_attn<<<dim3(32, 8), 256, SMEM_ATTN>>>(x, Wo, gamma, out);
}

// round 6
// speedup vs baseline: 7.2327x; 1.0929x over previous
#include <cuda_runtime.h>
#include <cuda_bf16.h>
#include <cstdint>

#define B_   8
#define C_   128
#define N_   4096
#define M_   1024
#define DQK  16
#define DV   64

// ---------------- device scratch ----------------
static __device__ __nv_bfloat16 g_theta_bf[B_ * N_ * DQK];   // [b][n][16] (pre-scaled by log2e)
static __device__ __nv_bfloat16 g_phi_bf  [B_ * M_ * DQK];   // [b][m][16]
static __device__ __nv_bfloat16 g_gT      [B_ * DV * M_];    // [b][ch][m]

// ---------------- helpers ----------------
__device__ __forceinline__ uint32_t smem_u32(const void* p) {
    uint32_t a;
    asm("{ .reg .u64 t; cvta.to.shared.u64 t, %1; cvt.u32.u64 %0, t; }" : "=r"(a) : "l"(p));
    return a;
}
__device__ __forceinline__ void cp16(uint32_t dst, const void* src) {
    asm volatile("cp.async.cg.shared.global [%0], [%1], 16;" :: "r"(dst), "l"(src));
}
#define CP_COMMIT() asm volatile("cp.async.commit_group;" ::: "memory")
#define CP_WAIT(n)  asm volatile("cp.async.wait_group %0;" :: "n"(n) : "memory")

__device__ __forceinline__ void mma_bf16(float d[4], const uint32_t a[4], const uint32_t b[2]) {
    asm volatile("mma.sync.aligned.m16n8k16.row.col.f32.bf16.bf16.f32 "
        "{%0,%1,%2,%3}, {%4,%5,%6,%7}, {%8,%9}, {%0,%1,%2,%3};"
        : "+f"(d[0]), "+f"(d[1]), "+f"(d[2]), "+f"(d[3])
        : "r"(a[0]), "r"(a[1]), "r"(a[2]), "r"(a[3]), "r"(b[0]), "r"(b[1]));
}
__device__ __forceinline__ uint32_t packbf(float lo, float hi) {
    uint32_t r;
    asm("cvt.rn.satfinite.bf16x2.f32 %0, %1, %2;" : "=r"(r) : "f"(hi), "f"(lo));
    return r;
}
__device__ __forceinline__ void ldsm_x4(uint32_t r[4], uint32_t addr) {
    asm volatile("ldmatrix.sync.aligned.m8n8.x4.shared.b16 {%0,%1,%2,%3}, [%4];"
        : "=r"(r[0]), "=r"(r[1]), "=r"(r[2]), "=r"(r[3]) : "r"(addr));
}
__device__ __forceinline__ void ldsm_x2t(uint32_t r[2], uint32_t addr) {
    asm volatile("ldmatrix.sync.aligned.m8n8.x2.trans.shared.b16 {%0,%1}, [%2];"
        : "=r"(r[0]), "=r"(r[1]) : "r"(addr));
}
__device__ __forceinline__ float ex2f(float v) {
    float r; asm("ex2.approx.ftz.f32 %0, %1;" : "=f"(r) : "f"(v)); return r;
}

// ============================================================================
// Kernel 1: all projections as one bf16 tensor-core GEMM + fused 2x2 pooling.
// W_theta rows pre-scaled by log2(e) so attention can use ex2 directly.
// ============================================================================
#define PROJ_WS   34816
#define SMEM_PROJ 60928

__global__ void __launch_bounds__(256) k_proj(const float* __restrict__ x,
                       const float* __restrict__ Wth,
                       const float* __restrict__ Wph, const float* __restrict__ Wg) {
    extern __shared__ __align__(16) unsigned char smem[];
    __nv_bfloat16* xs = (__nv_bfloat16*)smem;               // [128][136]
    __nv_bfloat16* ws = (__nv_bfloat16*)(smem + PROJ_WS);   // [96][136]
    int tid = threadIdx.x, b = blockIdx.y, bx = blockIdx.x;
    int n0 = bx * 128;

#pragma unroll
    for (int k = 0; k < 12; k++) {
        int e = k * 256 + tid;
        int row = e >> 5, c4 = e & 31;
        const float* src = (row < 16) ? &Wth[row * 128]
                         : (row < 32) ? &Wph[(row - 16) * 128]
                                      : &Wg[(row - 32) * 128];
        float sc = (row < 16) ? 1.4426950408889634f : 1.0f;
        float4 v = *(const float4*)&src[c4 * 4];
        uint32_t* d = (uint32_t*)&ws[row * 136 + c4 * 4];
        d[0] = packbf(v.x * sc, v.y * sc); d[1] = packbf(v.z * sc, v.w * sc);
    }
    const float* xp = x + ((size_t)b * C_) * N_ + n0;
#pragma unroll
    for (int k = 0; k < 16; k++) {
        int e = k * 256 + tid;
        int ch = e >> 5, p4 = e & 31;
        float4 v = *(const float4*)&xp[(size_t)ch * N_ + p4 * 4];
        uint32_t* d = (uint32_t*)&xs[ch * 136 + p4 * 4];
        d[0] = packbf(v.x, v.y); d[1] = packbf(v.z, v.w);
    }
    __syncthreads();

    int warp = tid >> 5, lane = tid & 31, g = lane >> 2, t = lane & 3;
    int px0 = warp * 16;
    int aq = lane >> 3;
    int ar = (aq & 1) * 8 + (lane & 7), ac = (aq >> 1) * 8;
    int bl = lane & 15;

    float acc[6][2][4];
#pragma unroll
    for (int mi = 0; mi < 6; mi++)
#pragma unroll
        for (int ni = 0; ni < 2; ni++)
#pragma unroll
            for (int i = 0; i < 4; i++) acc[mi][ni][i] = 0.f;

#pragma unroll
    for (int k0 = 0; k0 < 128; k0 += 16) {
        uint32_t bf[2][2];
#pragma unroll
        for (int ni = 0; ni < 2; ni++)
            ldsm_x2t(bf[ni], smem_u32(&xs[(k0 + bl) * 136 + px0 + ni * 8]));
#pragma unroll
        for (int mi = 0; mi < 6; mi++) {
            uint32_t af[4];
            ldsm_x4(af, smem_u32(&ws[(mi * 16 + ar) * 136 + k0 + ac]));
            mma_bf16(acc[mi][0], af, bf[0]);
            mma_bf16(acc[mi][1], af, bf[1]);
        }
    }

#pragma unroll
    for (int ni = 0; ni < 2; ni++) {
        int px = px0 + ni * 8 + 2 * t;
        __nv_bfloat16* base = &g_theta_bf[((size_t)b * N_ + n0 + px) * DQK];
        base[g]          = __float2bfloat16(acc[0][ni][0]);
        base[16 + g]     = __float2bfloat16(acc[0][ni][1]);
        base[g + 8]      = __float2bfloat16(acc[0][ni][2]);
        base[16 + g + 8] = __float2bfloat16(acc[0][ni][3]);
    }

    __syncthreads();
    __nv_bfloat16* st = xs;
#pragma unroll
    for (int mi = 1; mi < 6; mi++)
#pragma unroll
        for (int ni = 0; ni < 2; ni++) {
            int ro = mi * 16 - 16, pxx = px0 + ni * 8 + 2 * t;
            *(uint32_t*)&st[(ro + g) * 136 + pxx]     = packbf(acc[mi][ni][0], acc[mi][ni][1]);
            *(uint32_t*)&st[(ro + g + 8) * 136 + pxx] = packbf(acc[mi][ni][2], acc[mi][ni][3]);
        }
    __syncthreads();

    int cell0 = bx * 32;
#pragma unroll
    for (int k = 0; k < 10; k++) {
        int e = k * 256 + tid;
        int o = e >> 5, q = e & 31;
        __nv_bfloat162 v0 = *(__nv_bfloat162*)&st[o * 136 + 2 * q];
        __nv_bfloat162 v1 = *(__nv_bfloat162*)&st[o * 136 + 64 + 2 * q];
        float m = fmaxf(fmaxf(__low2float(v0), __high2float(v0)),
                        fmaxf(__low2float(v1), __high2float(v1)));
        if (o < 16)
            g_phi_bf[((size_t)b * M_ + cell0 + q) * DQK + o] = __float2bfloat16(m);
        else
            g_gT[((size_t)b * DV + (o - 16)) * M_ + cell0 + q] = __float2bfloat16(m);
    }
}

// ============================================================================
// Kernel 2: fused attention + W_o + residual.  8 warps x 16 queries.
// Main loop uses ldmatrix.x4 for all fragment loads; exp via ex2 (prescaled).
// ============================================================================
#define TH_OFF   0
#define PHI_OFF  4096
#define BIG_OFF  12288
#define WO_OFF   47104
#define SMEM_ATTN 64512

__global__ void __launch_bounds__(256) k_attn(const float* __restrict__ x,
                      const float* __restrict__ Wo,
                      const float* __restrict__ gammap, float* __restrict__ out) {
    extern __shared__ __align__(16) unsigned char smem[];
    int tid = threadIdx.x, b = blockIdx.y, q0 = blockIdx.x * 128;
    int warp = tid >> 5, lane = tid & 31, g = lane >> 2, t = lane & 3;
    uint32_t sb = smem_u32(smem);

    // ldmatrix lane maps
    int lo  = ((lane >> 4) & 1) * 8 + (lane & 7);   // B-tile row within 16
    int hi8 = ((lane >> 3) & 1) * 8;                // B-tile col half
    int arow = ((lane >> 3) & 1) * 8 + (lane & 7);  // A-tile row within 16
    int acol = ((lane >> 4) & 1) * 8;               // A-tile col half

    cp16(sb + TH_OFF + tid * 16,
         (const char*)&g_theta_bf[((size_t)b * N_ + q0) * DQK] + tid * 16);
    auto issue_chunk = [&](int c, int buf) {
        const char* gsrc = (const char*)&g_gT[((size_t)b * DV) * M_ + c * 128];
        uint32_t gdst = sb + BIG_OFF + buf * 17408;
#pragma unroll
        for (int r = 0; r < 4; r++) {
            int i = r * 256 + tid;
            int ch = i >> 4, off = i & 15;
            cp16(gdst + ch * 272 + off * 16, gsrc + (size_t)ch * 2048 + off * 16);
        }
        cp16(sb + PHI_OFF + buf * 4096 + tid * 16,
             (const char*)&g_phi_bf[((size_t)b * M_ + c * 128) * DQK] + tid * 16);
    };
    issue_chunk(0, 0); CP_COMMIT();

    uint32_t thA[4];
    float o[8][4];
#pragma unroll
    for (int n = 0; n < 8; n++)
#pragma unroll
        for (int i = 0; i < 4; i++) o[n][i] = 0.f;
    float z[2] = {0.f, 0.f};

    for (int c = 0; c < 8; c++) {
        int buf = c & 1;
        if (c < 7) { issue_chunk(c + 1, buf ^ 1); CP_COMMIT(); CP_WAIT(1); }
        else       { CP_WAIT(0); }
        __syncthreads();

        if (c == 0) {
            const __nv_bfloat16* ths = (const __nv_bfloat16*)(smem + TH_OFF);
            ldsm_x4(thA, smem_u32(&ths[(warp * 16 + arow) * 16 + acol]));
        }
        const __nv_bfloat16* phis = (const __nv_bfloat16*)(smem + PHI_OFF + buf * 4096);
        const __nv_bfloat16* gts  = (const __nv_bfloat16*)(smem + BIG_OFF + buf * 17408);

#pragma unroll
        for (int kt = 0; kt < 8; kt++) {
            // phi B-fragments: one x4 = both key sub-tiles
            uint32_t pbq[4];
            ldsm_x4(pbq, smem_u32(&phis[(kt * 16 + lo) * 16 + hi8]));
            // G B-fragments: 4 x4 = 8 ch-tiles (independent of S chain)
            uint32_t gbq[4][4];
#pragma unroll
            for (int np = 0; np < 4; np++)
                ldsm_x4(gbq[np], smem_u32(&gts[(np * 16 + lo) * 136 + kt * 16 + hi8]));

            float s0[4] = {0.f, 0.f, 0.f, 0.f}, s1[4] = {0.f, 0.f, 0.f, 0.f};
            mma_bf16(s0, thA, &pbq[0]);
            mma_bf16(s1, thA, &pbq[2]);

            float e00 = ex2f(s0[0]), e01 = ex2f(s0[1]);
            float e02 = ex2f(s0[2]), e03 = ex2f(s0[3]);
            float e10 = ex2f(s1[0]), e11 = ex2f(s1[1]);
            float e12 = ex2f(s1[2]), e13 = ex2f(s1[3]);
            z[0] += (e00 + e01) + (e10 + e11);
            z[1] += (e02 + e03) + (e12 + e13);
            uint32_t pa[4];
            pa[0] = packbf(e00, e01); pa[1] = packbf(e02, e03);
            pa[2] = packbf(e10, e11); pa[3] = packbf(e12, e13);
#pragma unroll
            for (int np = 0; np < 4; np++) {
                mma_bf16(o[2*np],   pa, &gbq[np][0]);
                mma_bf16(o[2*np+1], pa, &gbq[np][2]);
            }
        }
        __syncthreads();
    }

    // ---------------- epilogue: normalize, W_o GEMM, residual ----------------
    z[0] += __shfl_xor_sync(0xffffffffu, z[0], 1);
    z[0] += __shfl_xor_sync(0xffffffffu, z[0], 2);
    z[1] += __shfl_xor_sync(0xffffffffu, z[1], 1);
    z[1] += __shfl_xor_sync(0xffffffffu, z[1], 2);
    float inv0 = 1.f / z[0], inv1 = 1.f / z[1];

    {
        uint32_t* wo32 = (uint32_t*)(smem + WO_OFF);
        int row = tid >> 1, half = tid & 1;
        const float2* wsrc = (const float2*)(Wo + (size_t)row * 64) + half * 16;
#pragma unroll
        for (int j = 0; j < 16; j++) {
            float2 v = wsrc[j];
            wo32[row * 34 + half * 16 + j] = packbf(v.x, v.y);
        }
    }
    uint32_t pA[4][4];
#pragma unroll
    for (int kt = 0; kt < 4; kt++) {
        pA[kt][0] = packbf(o[2*kt][0]   * inv0, o[2*kt][1]   * inv0);
        pA[kt][1] = packbf(o[2*kt][2]   * inv1, o[2*kt][3]   * inv1);
        pA[kt][2] = packbf(o[2*kt+1][0] * inv0, o[2*kt+1][1] * inv0);
        pA[kt][3] = packbf(o[2*kt+1][2] * inv1, o[2*kt+1][3] * inv1);
    }
    float gamma = *gammap;
    __syncthreads();

    const uint32_t* wo32 = (const uint32_t*)(smem + WO_OFF);
    float* st = (float*)smem;

#pragma unroll
    for (int h = 0; h < 2; h++) {
        float acc[8][4];
#pragma unroll
        for (int nb = 0; nb < 8; nb++)
#pragma unroll
            for (int i = 0; i < 4; i++) acc[nb][i] = 0.f;
#pragma unroll
        for (int nb = 0; nb < 8; nb++) {
            int row = (h * 8 + nb) * 8 + g;
#pragma unroll
            for (int kt = 0; kt < 4; kt++) {
                uint32_t gb[2];
                gb[0] = wo32[row * 34 + kt * 8 + t];
                gb[1] = wo32[row * 34 + kt * 8 + t + 4];
                mma_bf16(acc[nb], pA[kt], gb);
            }
        }
        __syncthreads();
#pragma unroll
        for (int nb = 0; nb < 8; nb++) {
            int ch = nb * 8 + 2 * t, q = warp * 16 + g;
            st[ch * 132 + q]           = acc[nb][0];
            st[(ch + 1) * 132 + q]     = acc[nb][1];
            st[ch * 132 + q + 8]       = acc[nb][2];
            st[(ch + 1) * 132 + q + 8] = acc[nb][3];
        }
        __syncthreads();
        const float* xs = x + ((size_t)b * C_ + h * 64) * N_ + q0;
        float* op = out + ((size_t)b * C_ + h * 64) * N_ + q0;
#pragma unroll
        for (int i = 0; i < 8; i++) {
            int e = i * 256 + tid;
            int ch = e >> 5, q4 = (e & 31) * 4;
            float4 v = *(const float4*)&st[ch * 132 + q4];
            float4 xv = *(const float4*)&xs[(size_t)ch * N_ + q4];
            v.x = fmaf(gamma, v.x, xv.x); v.y = fmaf(gamma, v.y, xv.y);
            v.z = fmaf(gamma, v.z, xv.z); v.w = fmaf(gamma, v.w, xv.w);
            *(float4*)&op[(size_t)ch * N_ + q4] = v;
        }
    }
}

// ---------------------------------------------------------------------------
extern "C" void kernel_launch(void* const* d_in, const int* in_sizes, int n_in,
                              void* d_out, int out_size) {
    const float* x     = (const float*)d_in[0];
    const float* Wth   = (const float*)d_in[1];
    const float* Wph   = (const float*)d_in[2];
    const float* Wg    = (const float*)d_in[3];
    const float* Wo    = (const float*)d_in[4];
    const float* gamma = (const float*)d_in[5];
    float* out = (float*)d_out;

    static int configured = 0;
    if (!configured) {
        cudaFuncSetAttribute(k_proj, cudaFuncAttributeMaxDynamicSharedMemorySize, SMEM_PROJ);
        cudaFuncSetAttribute(k_attn, cudaFuncAttributeMaxDynamicSharedMemorySize, SMEM_ATTN);
        configured = 1;
    }

    k_proj<<<dim3(32, 8), 256, SMEM_PROJ>>>(x, Wth, Wph, Wg);
    k_attn<<<dim3(32, 8), 256, SMEM_ATTN>>>(x, Wo, gamma, out);
}